// round 12
// baseline (speedup 1.0000x reference)
#include <cuda_runtime.h>

// GraphAttentionPooling: B=32, N=3072, F=256, P=3 -> S=1024, 32768 windows.
// R7 topology (best: 21.0us): persistent 444 blocks (3/SM) x 256 thr,
// grid-stride, depth-1 register double-buffer.
// R12: L2 warming via the .L2::256B prefetch qualifier ON the loads
// (each LDG pulls its line + the adjacent 128B line into L2, registerless),
// replacing all explicit prefetch.global.L2 instructions.

#define F_DIM 256
#define P_DIM 3
#define NUM_SMS 148
#define BLOCKS_PER_SM 3
#define THREADS_PER_BLOCK 256

__device__ __forceinline__ float4 ldcs_pf256(const float4* p) {
    float4 v;
    asm volatile("ld.global.cs.L2::256B.v4.f32 {%0,%1,%2,%3}, [%4];"
                 : "=f"(v.x), "=f"(v.y), "=f"(v.z), "=f"(v.w) : "l"(p));
    return v;
}

__device__ __forceinline__ float warp_reduce_sum(float v) {
    #pragma unroll
    for (int off = 16; off > 0; off >>= 1)
        v += __shfl_xor_sync(0xFFFFFFFFu, v, off);
    return v;
}

__device__ __forceinline__ float dot8(float4 a, float4 b, float4 wa, float4 wb) {
    float s = a.x * wa.x;
    s = fmaf(a.y, wa.y, s);
    s = fmaf(a.z, wa.z, s);
    s = fmaf(a.w, wa.w, s);
    s = fmaf(b.x, wb.x, s);
    s = fmaf(b.y, wb.y, s);
    s = fmaf(b.z, wb.z, s);
    s = fmaf(b.w, wb.w, s);
    return s;
}

__global__ void __launch_bounds__(THREADS_PER_BLOCK, BLOCKS_PER_SM)
gap_kernel(const float* __restrict__ x,
           const float* __restrict__ Ww,
           const float* __restrict__ Wb,
           float* __restrict__ out,
           int n_windows) {
    const int warp_id = (blockIdx.x * blockDim.x + threadIdx.x) >> 5;
    const int lane    = threadIdx.x & 31;
    const int n_warps = (int)((gridDim.x * blockDim.x) >> 5);

    const int fv = lane * 2;  // float4 index within a row (row = 64 float4)

    const float4* Wv = reinterpret_cast<const float4*>(Ww);
    const float4 wa = Wv[fv], wb = Wv[fv + 1];
    const float bias = Wb[0];

    const float4* xbase = reinterpret_cast<const float4*>(x);
    float4*       obase = reinterpret_cast<float4*>(out);

    int w = warp_id;
    if (w >= n_windows) return;

    // Register prefetch of window 0 (window stride = 192 float4).
    // Each load also L2-prefetches the adjacent 128B line (registerless warming).
    const float4* xin0 = xbase + (long long)w * 192 + fv;
    float4 n0a = ldcs_pf256(xin0 + 0 * 64), n0b = ldcs_pf256(xin0 + 0 * 64 + 1);
    float4 n1a = ldcs_pf256(xin0 + 1 * 64), n1b = ldcs_pf256(xin0 + 1 * 64 + 1);
    float4 n2a = ldcs_pf256(xin0 + 2 * 64), n2b = ldcs_pf256(xin0 + 2 * 64 + 1);

    for (; w < n_windows; w += n_warps) {
        // Current window = last register prefetch.
        float4 r0a = n0a, r0b = n0b;
        float4 r1a = n1a, r1b = n1b;
        float4 r2a = n2a, r2b = n2b;

        // Register prefetch of next window BEFORE the dependent compute chain.
        {
            int wn = w + n_warps;
            wn = (wn < n_windows) ? wn : w;  // last iter: reload self (L2 hit)
            const float4* nx = xbase + (long long)wn * 192 + fv;
            n0a = ldcs_pf256(nx + 0 * 64); n0b = ldcs_pf256(nx + 0 * 64 + 1);
            n1a = ldcs_pf256(nx + 1 * 64); n1b = ldcs_pf256(nx + 1 * 64 + 1);
            n2a = ldcs_pf256(nx + 2 * 64); n2b = ldcs_pf256(nx + 2 * 64 + 1);
        }

        // Scores: per-lane partials + butterfly reduce (3 independent chains).
        float s0 = warp_reduce_sum(dot8(r0a, r0b, wa, wb)) + bias;
        float s1 = warp_reduce_sum(dot8(r1a, r1b, wa, wb)) + bias;
        float s2 = warp_reduce_sum(dot8(r2a, r2b, wa, wb)) + bias;

        // Softmax over 3 scores.
        float m = fmaxf(s0, fmaxf(s1, s2));
        float e0 = __expf(s0 - m);
        float e1 = __expf(s1 - m);
        float e2 = __expf(s2 - m);
        float inv = 1.0f / (e0 + e1 + e2);
        float a0 = e0 * inv, a1 = e1 * inv, a2 = e2 * inv;

        // Weighted combine.
        float4 oa, ob;
        oa.x = fmaf(r2a.x, a2, fmaf(r1a.x, a1, r0a.x * a0));
        oa.y = fmaf(r2a.y, a2, fmaf(r1a.y, a1, r0a.y * a0));
        oa.z = fmaf(r2a.z, a2, fmaf(r1a.z, a1, r0a.z * a0));
        oa.w = fmaf(r2a.w, a2, fmaf(r1a.w, a1, r0a.w * a0));
        ob.x = fmaf(r2b.x, a2, fmaf(r1b.x, a1, r0b.x * a0));
        ob.y = fmaf(r2b.y, a2, fmaf(r1b.y, a1, r0b.y * a0));
        ob.z = fmaf(r2b.z, a2, fmaf(r1b.z, a1, r0b.z * a0));
        ob.w = fmaf(r2b.w, a2, fmaf(r1b.w, a1, r0b.w * a0));

        float4* o = obase + (long long)w * 64 + fv;
        __stcs(o,     oa);
        __stcs(o + 1, ob);
    }
}

extern "C" void kernel_launch(void* const* d_in, const int* in_sizes, int n_in,
                              void* d_out, int out_size) {
    const float* x  = (const float*)d_in[0];  // [32, 3072, 256]
    const float* Ww = (const float*)d_in[1];  // [256]
    const float* Wb = (const float*)d_in[2];  // [1]
    float* out = (float*)d_out;               // [32, 1024, 256, 1]

    const int n_windows = in_sizes[0] / (P_DIM * F_DIM);  // 32768
    const int blocks = NUM_SMS * BLOCKS_PER_SM;           // 444, exact-fit one wave

    gap_kernel<<<blocks, THREADS_PER_BLOCK>>>(x, Ww, Wb, out, n_windows);
}

// round 13
// speedup vs baseline: 1.1614x; 1.1614x over previous
#include <cuda_runtime.h>

// GraphAttentionPooling: B=32, N=3072, F=256, P=3 -> S=1024, 32768 windows.
// Champion topology (R7, 21.0us): persistent 444 blocks (3/SM) x 256 thr,
// grid-stride, depth-1 register double-buffer, explicit prefetch.global.L2
// PD iterations ahead. R13: inner loop uses pointer increments + iteration
// countdown (no per-iter 64-bit index products / bounds checks).

#define F_DIM 256
#define P_DIM 3
#define NUM_SMS 148
#define BLOCKS_PER_SM 3
#define THREADS_PER_BLOCK 256
#define PD 4   // prefetch distance in grid-stride iterations

__device__ __forceinline__ float warp_reduce_sum(float v) {
    #pragma unroll
    for (int off = 16; off > 0; off >>= 1)
        v += __shfl_xor_sync(0xFFFFFFFFu, v, off);
    return v;
}

__device__ __forceinline__ float dot8(float4 a, float4 b, float4 wa, float4 wb) {
    float s = a.x * wa.x;
    s = fmaf(a.y, wa.y, s);
    s = fmaf(a.z, wa.z, s);
    s = fmaf(a.w, wa.w, s);
    s = fmaf(b.x, wb.x, s);
    s = fmaf(b.y, wb.y, s);
    s = fmaf(b.z, wb.z, s);
    s = fmaf(b.w, wb.w, s);
    return s;
}

__global__ void __launch_bounds__(THREADS_PER_BLOCK, BLOCKS_PER_SM)
gap_kernel(const float* __restrict__ x,
           const float* __restrict__ Ww,
           const float* __restrict__ Wb,
           float* __restrict__ out,
           int n_windows) {
    const int warp_id = (blockIdx.x * blockDim.x + threadIdx.x) >> 5;
    const int lane    = threadIdx.x & 31;
    const int n_warps = (int)((gridDim.x * blockDim.x) >> 5);

    if (warp_id >= n_windows) return;

    const int fv = lane * 2;  // float4 index within a row (row = 64 float4)

    const float4* Wv = reinterpret_cast<const float4*>(Ww);
    const float4 wa = Wv[fv], wb = Wv[fv + 1];
    const float bias = Wb[0];

    // Per-warp iteration count: niter = ceil((n_windows - warp_id) / n_warps)
    const int niter = (n_windows - warp_id + n_warps - 1) / n_warps;

    // Strides in bytes / elements for one grid-stride step.
    const long long stride_win  = (long long)n_warps * 3072;   // x bytes
    const long long stride_out  = (long long)n_warps * 64;     // out float4s

    // Base pointers for this warp.
    const char*   xw   = (const char*)x + (long long)warp_id * 3072;
    const float4* xld  = reinterpret_cast<const float4*>(xw) + fv;   // load ptr (window i)
    const char*   xpf  = xw + (long long)PD * stride_win + lane * 128; // prefetch ptr (window i+PD)
    float4*       oput = reinterpret_cast<float4*>(out) + (long long)warp_id * 64 + fv;

    // Prologue: L2-prefetch windows 0..PD-1 of this warp's stream.
    // Window = 3072 B = 24 lines; lanes 0..23 take one line each.
    if (lane < 24) {
        const char* p0 = xw + lane * 128;
        #pragma unroll
        for (int d = 0; d < PD; d++) {
            if (d < niter) {
                const char* p = p0 + (long long)d * stride_win;
                asm volatile("prefetch.global.L2 [%0];" :: "l"(p));
            }
        }
    }

    // Register prefetch of window 0.
    float4 n0a = __ldcs(xld +   0), n0b = __ldcs(xld +   1);
    float4 n1a = __ldcs(xld +  64), n1b = __ldcs(xld +  65);
    float4 n2a = __ldcs(xld + 128), n2b = __ldcs(xld + 129);

    for (int i = 0; i < niter; i++) {
        // L2-prefetch window i+PD (registerless; predicate is a countdown compare).
        if (i + PD < niter && lane < 24) {
            asm volatile("prefetch.global.L2 [%0];" :: "l"(xpf));
        }
        xpf += stride_win;

        // Current window = last register prefetch.
        float4 r0a = n0a, r0b = n0b;
        float4 r1a = n1a, r1b = n1b;
        float4 r2a = n2a, r2b = n2b;

        // Register prefetch of window i+1 BEFORE the dependent compute chain.
        {
            const float4* nx = (i + 1 < niter)
                ? (const float4*)((const char*)xld + stride_win)
                : xld;  // last iter: reload self (L2 hit, harmless)
            n0a = __ldcs(nx +   0); n0b = __ldcs(nx +   1);
            n1a = __ldcs(nx +  64); n1b = __ldcs(nx +  65);
            n2a = __ldcs(nx + 128); n2b = __ldcs(nx + 129);
        }
        xld = (const float4*)((const char*)xld + stride_win);

        // Scores: per-lane partials + butterfly reduce (3 independent chains).
        float s0 = warp_reduce_sum(dot8(r0a, r0b, wa, wb)) + bias;
        float s1 = warp_reduce_sum(dot8(r1a, r1b, wa, wb)) + bias;
        float s2 = warp_reduce_sum(dot8(r2a, r2b, wa, wb)) + bias;

        // Softmax over 3 scores.
        float m = fmaxf(s0, fmaxf(s1, s2));
        float e0 = __expf(s0 - m);
        float e1 = __expf(s1 - m);
        float e2 = __expf(s2 - m);
        float inv = 1.0f / (e0 + e1 + e2);
        float a0 = e0 * inv, a1 = e1 * inv, a2 = e2 * inv;

        // Weighted combine.
        float4 oa, ob;
        oa.x = fmaf(r2a.x, a2, fmaf(r1a.x, a1, r0a.x * a0));
        oa.y = fmaf(r2a.y, a2, fmaf(r1a.y, a1, r0a.y * a0));
        oa.z = fmaf(r2a.z, a2, fmaf(r1a.z, a1, r0a.z * a0));
        oa.w = fmaf(r2a.w, a2, fmaf(r1a.w, a1, r0a.w * a0));
        ob.x = fmaf(r2b.x, a2, fmaf(r1b.x, a1, r0b.x * a0));
        ob.y = fmaf(r2b.y, a2, fmaf(r1b.y, a1, r0b.y * a0));
        ob.z = fmaf(r2b.z, a2, fmaf(r1b.z, a1, r0b.z * a0));
        ob.w = fmaf(r2b.w, a2, fmaf(r1b.w, a1, r0b.w * a0));

        __stcs(oput,     oa);
        __stcs(oput + 1, ob);
        oput += stride_out;
    }
}

extern "C" void kernel_launch(void* const* d_in, const int* in_sizes, int n_in,
                              void* d_out, int out_size) {
    const float* x  = (const float*)d_in[0];  // [32, 3072, 256]
    const float* Ww = (const float*)d_in[1];  // [256]
    const float* Wb = (const float*)d_in[2];  // [1]
    float* out = (float*)d_out;               // [32, 1024, 256, 1]

    const int n_windows = in_sizes[0] / (P_DIM * F_DIM);  // 32768
    const int blocks = NUM_SMS * BLOCKS_PER_SM;           // 444, exact-fit one wave

    gap_kernel<<<blocks, THREADS_PER_BLOCK>>>(x, Ww, Wb, out, n_windows);
}

// round 14
// speedup vs baseline: 1.1756x; 1.0122x over previous
#include <cuda_runtime.h>

// GraphAttentionPooling: B=32, N=3072, F=256, P=3 -> S=1024, 32768 windows.
// Champion topology (R7, 21.0us): persistent 444 blocks (3/SM) x 256 thr,
// grid-stride, depth-1 register double-buffer, explicit prefetch.global.L2.
// R14: PD=6 (longer prefetch lead) + peeled final iteration (no clamped
// self-reload -> ~11MB less L2 read traffic and a shorter warp tail).

#define F_DIM 256
#define P_DIM 3
#define NUM_SMS 148
#define BLOCKS_PER_SM 3
#define THREADS_PER_BLOCK 256
#define PD 6   // prefetch distance in grid-stride iterations

__device__ __forceinline__ float warp_reduce_sum(float v) {
    #pragma unroll
    for (int off = 16; off > 0; off >>= 1)
        v += __shfl_xor_sync(0xFFFFFFFFu, v, off);
    return v;
}

__device__ __forceinline__ float dot8(float4 a, float4 b, float4 wa, float4 wb) {
    float s = a.x * wa.x;
    s = fmaf(a.y, wa.y, s);
    s = fmaf(a.z, wa.z, s);
    s = fmaf(a.w, wa.w, s);
    s = fmaf(b.x, wb.x, s);
    s = fmaf(b.y, wb.y, s);
    s = fmaf(b.z, wb.z, s);
    s = fmaf(b.w, wb.w, s);
    return s;
}

// Softmax over 3 + weighted combine + streaming store for one window.
__device__ __forceinline__ void finish_window(
    float s0, float s1, float s2,
    float4 r0a, float4 r0b, float4 r1a, float4 r1b, float4 r2a, float4 r2b,
    float4* o)
{
    float m = fmaxf(s0, fmaxf(s1, s2));
    float e0 = __expf(s0 - m);
    float e1 = __expf(s1 - m);
    float e2 = __expf(s2 - m);
    float inv = 1.0f / (e0 + e1 + e2);
    float a0 = e0 * inv, a1 = e1 * inv, a2 = e2 * inv;

    float4 oa, ob;
    oa.x = fmaf(r2a.x, a2, fmaf(r1a.x, a1, r0a.x * a0));
    oa.y = fmaf(r2a.y, a2, fmaf(r1a.y, a1, r0a.y * a0));
    oa.z = fmaf(r2a.z, a2, fmaf(r1a.z, a1, r0a.z * a0));
    oa.w = fmaf(r2a.w, a2, fmaf(r1a.w, a1, r0a.w * a0));
    ob.x = fmaf(r2b.x, a2, fmaf(r1b.x, a1, r0b.x * a0));
    ob.y = fmaf(r2b.y, a2, fmaf(r1b.y, a1, r0b.y * a0));
    ob.z = fmaf(r2b.z, a2, fmaf(r1b.z, a1, r0b.z * a0));
    ob.w = fmaf(r2b.w, a2, fmaf(r1b.w, a1, r0b.w * a0));

    __stcs(o,     oa);
    __stcs(o + 1, ob);
}

__global__ void __launch_bounds__(THREADS_PER_BLOCK, BLOCKS_PER_SM)
gap_kernel(const float* __restrict__ x,
           const float* __restrict__ Ww,
           const float* __restrict__ Wb,
           float* __restrict__ out,
           int n_windows) {
    const int warp_id = (blockIdx.x * blockDim.x + threadIdx.x) >> 5;
    const int lane    = threadIdx.x & 31;
    const int n_warps = (int)((gridDim.x * blockDim.x) >> 5);

    if (warp_id >= n_windows) return;

    const int fv = lane * 2;  // float4 index within a row (row = 64 float4)

    const float4* Wv = reinterpret_cast<const float4*>(Ww);
    const float4 wa = Wv[fv], wb = Wv[fv + 1];
    const float bias = Wb[0];

    const float4* xbase = reinterpret_cast<const float4*>(x);
    float4*       obase = reinterpret_cast<float4*>(out);

    // Prologue: L2-prefetch the first PD windows of this warp's stream.
    // Window = 3072 B = 24 lines; lanes 0..23 take one 128B line each.
    if (lane < 24) {
        #pragma unroll
        for (int d = 0; d < PD; d++) {
            long long wi = warp_id + (long long)d * n_warps;
            if (wi < n_windows) {
                const char* p = (const char*)x + wi * 3072 + lane * 128;
                asm volatile("prefetch.global.L2 [%0];" :: "l"(p));
            }
        }
    }

    // Register prefetch of window 0.
    int w = warp_id;
    const float4* xin0 = xbase + (long long)w * 192 + fv;
    float4 n0a = __ldcs(xin0 +   0), n0b = __ldcs(xin0 +   1);
    float4 n1a = __ldcs(xin0 +  64), n1b = __ldcs(xin0 +  65);
    float4 n2a = __ldcs(xin0 + 128), n2b = __ldcs(xin0 + 129);

    // Main loop: all iterations that have a successor window.
    for (; w + n_warps < n_windows; w += n_warps) {
        // L2-prefetch the window PD iterations ahead (registerless).
        {
            long long wp = w + (long long)PD * n_warps;
            if (wp < n_windows && lane < 24) {
                const char* p = (const char*)x + wp * 3072 + lane * 128;
                asm volatile("prefetch.global.L2 [%0];" :: "l"(p));
            }
        }

        // Current window = last register prefetch.
        float4 r0a = n0a, r0b = n0b;
        float4 r1a = n1a, r1b = n1b;
        float4 r2a = n2a, r2b = n2b;

        // Register prefetch of the next window BEFORE the compute chain.
        {
            const float4* nx = xbase + (long long)(w + n_warps) * 192 + fv;
            n0a = __ldcs(nx +   0); n0b = __ldcs(nx +   1);
            n1a = __ldcs(nx +  64); n1b = __ldcs(nx +  65);
            n2a = __ldcs(nx + 128); n2b = __ldcs(nx + 129);
        }

        float s0 = warp_reduce_sum(dot8(r0a, r0b, wa, wb)) + bias;
        float s1 = warp_reduce_sum(dot8(r1a, r1b, wa, wb)) + bias;
        float s2 = warp_reduce_sum(dot8(r2a, r2b, wa, wb)) + bias;

        finish_window(s0, s1, s2, r0a, r0b, r1a, r1b, r2a, r2b,
                      obase + (long long)w * 64 + fv);
    }

    // Peeled final iteration: consume the last prefetched window, no reload.
    {
        float s0 = warp_reduce_sum(dot8(n0a, n0b, wa, wb)) + bias;
        float s1 = warp_reduce_sum(dot8(n1a, n1b, wa, wb)) + bias;
        float s2 = warp_reduce_sum(dot8(n2a, n2b, wa, wb)) + bias;

        finish_window(s0, s1, s2, n0a, n0b, n1a, n1b, n2a, n2b,
                      obase + (long long)w * 64 + fv);
    }
}

extern "C" void kernel_launch(void* const* d_in, const int* in_sizes, int n_in,
                              void* d_out, int out_size) {
    const float* x  = (const float*)d_in[0];  // [32, 3072, 256]
    const float* Ww = (const float*)d_in[1];  // [256]
    const float* Wb = (const float*)d_in[2];  // [1]
    float* out = (float*)d_out;               // [32, 1024, 256, 1]

    const int n_windows = in_sizes[0] / (P_DIM * F_DIM);  // 32768
    const int blocks = NUM_SMS * BLOCKS_PER_SM;           // 444, exact-fit one wave

    gap_kernel<<<blocks, THREADS_PER_BLOCK>>>(x, Ww, Wb, out, n_windows);
}